// round 15
// baseline (speedup 1.0000x reference)
#include <cuda_runtime.h>
#include <cstdint>

// Problem constants: B=32, N=M=4096, d=3
#define BB     32
#define NPTS   4096
#define NBINS  512                // 8x8x8 equal-prob z-order cells
#define NCHK   512                // 8-target chunks per batch
#define CSZ    8
#define NGRP   64                 // groups of 8 chunks (64 targets)
#define TPB    512
#define CPB    8                  // CTAs per batch  (256 CTAs total)
#define NBLK1  128

#define BIGF 3.4028235e38f

// ---- persistent scratch (no allocations allowed) --------------------------
__device__ float4 g_tgtS [BB * NPTS];   // sorted targets {x, y, z, 0.5|t|^2}
__device__ float4 g_predS[BB * NPTS];   // sorted preds  {-x,-y,-z,  |p|^2}
__device__ int    g_pidx [BB * NPTS];   // original pred index per sorted slot
__device__ float  g_dist [BB * NPTS];   // per-pred nearest distance (orig order)
__device__ float  g_bsum [NBLK1];

// ---------------------------------------------------------------------------
// 8 equal-probability levels per axis (N(0,1) octiles). Exactness never
// depends on this — all bounds are data-derived AABBs.
// ---------------------------------------------------------------------------
__device__ __forceinline__ int qlvl8(float v) {
    return (v > -1.1503f) + (v > -0.6745f) + (v > -0.3186f) + (v > 0.0f) +
           (v >  0.3186f) + (v >  0.6745f) + (v >  1.1503f);
}
// key: L1 = coarse 4x4x4 cell, L2 = fine octant within -> 9-bit z-order-ish
__device__ __forceinline__ unsigned sort_key(float x, float y, float z) {
    int qx = qlvl8(x), qy = qlvl8(y), qz = qlvl8(z);
    int l1 = (qx >> 1) * 16 + (qy >> 1) * 4 + (qz >> 1);
    int l2 = (qx & 1) * 4 + (qy & 1) * 2 + (qz & 1);
    return (unsigned)(l1 * 8 + l2);
}

// ---------------------------------------------------------------------------
// P1: counting-sort by 3D cell key. One CTA per (batch, tensor).
// ---------------------------------------------------------------------------
__global__ __launch_bounds__(512) void bin_kernel(const float* __restrict__ pred,
                                                  const float* __restrict__ tgt) {
    __shared__ unsigned hist[NBINS];
    __shared__ unsigned wsum[512];

    int b      = blockIdx.x >> 1;
    int isPred = blockIdx.x & 1;
    const float* src = (isPred ? pred : tgt) + (size_t)b * NPTS * 3;
    int tid = threadIdx.x;

    if (tid < NBINS) hist[tid] = 0u;
    __syncthreads();

    unsigned mybin[8];
    #pragma unroll
    for (int j = 0; j < 8; j++) {
        int i = tid * 8 + j;
        mybin[j] = sort_key(src[3 * i], src[3 * i + 1], src[3 * i + 2]);
        atomicAdd(&hist[mybin[j]], 1u);
    }
    __syncthreads();

    unsigned s = (tid < NBINS) ? hist[tid] : 0u;
    wsum[tid] = s;
    __syncthreads();
    #pragma unroll
    for (int off = 1; off < 512; off <<= 1) {
        unsigned v = wsum[tid];
        unsigned a = (tid >= off) ? wsum[tid - off] : 0u;
        __syncthreads();
        wsum[tid] = v + a;
        __syncthreads();
    }
    if (tid < NBINS) hist[tid] = wsum[tid] - s;   // exclusive base
    __syncthreads();

    float4* dst = (isPred ? g_predS : g_tgtS) + b * NPTS;
    int*    pix = g_pidx + b * NPTS;
    #pragma unroll
    for (int j = 0; j < 8; j++) {
        int i = tid * 8 + j;
        unsigned pos = atomicAdd(&hist[mybin[j]], 1u);
        float x = src[3 * i], y = src[3 * i + 1], z = src[3 * i + 2];
        float n2 = x * x + y * y + z * z;
        if (isPred) {
            dst[pos] = make_float4(-x, -y, -z, n2);
            pix[pos] = i;
        } else {
            dst[pos] = make_float4(x, y, z, 0.5f * n2);
        }
    }
}

// ---------------------------------------------------------------------------
// P2: exact NN, two-level 3D AABB pruning.
//   r(p,t) = 0.5|t|^2 - p.t  (3 FFMA);  d^2 = |p|^2 + 2 r
// ---------------------------------------------------------------------------
__device__ __forceinline__ void eval_chunk8(const float4* __restrict__ ct,
                                            float4 p, float& m0, float& m1) {
    #pragma unroll
    for (int i = 0; i < CSZ; i += 2) {
        float4 ta = ct[i];
        float4 tb = ct[i + 1];
        float ra = __fmaf_rn(p.z, ta.z, ta.w);
        float rb = __fmaf_rn(p.z, tb.z, tb.w);
        ra = __fmaf_rn(p.y, ta.y, ra);
        rb = __fmaf_rn(p.y, tb.y, rb);
        ra = __fmaf_rn(p.x, ta.x, ra);
        rb = __fmaf_rn(p.x, tb.x, rb);
        m0 = fminf(m0, ra);
        m1 = fminf(m1, rb);
    }
}

// 3D point-to-box squared distance
__device__ __forceinline__ float pt_lb2(float4 bxy, float2 bz,
                                        float px, float py, float pz) {
    float dx = fmaxf(0.0f, fmaxf(bxy.x - px, px - bxy.y));
    float dy = fmaxf(0.0f, fmaxf(bxy.z - py, py - bxy.w));
    float dz = fmaxf(0.0f, fmaxf(bz.x - pz, pz - bz.y));
    return __fmaf_rn(dx, dx, __fmaf_rn(dy, dy, dz * dz));
}

// 3D box-to-box squared distance (chunk/group box vs warp box)
__device__ __forceinline__ float box_lb2(float4 bxy, float2 bz,
                                         float wmnx, float wmxx, float wmny,
                                         float wmxy, float wmnz, float wmxz) {
    float dx = fmaxf(0.0f, fmaxf(bxy.x - wmxx, wmnx - bxy.y));
    float dy = fmaxf(0.0f, fmaxf(bxy.z - wmxy, wmny - bxy.w));
    float dz = fmaxf(0.0f, fmaxf(bz.x - wmxz, wmnz - bz.y));
    return __fmaf_rn(dx, dx, __fmaf_rn(dy, dy, dz * dz));
}

__device__ __forceinline__ float warp_max(float v) {
    #pragma unroll
    for (int o = 16; o; o >>= 1)
        v = fmaxf(v, __shfl_xor_sync(0xffffffffu, v, o));
    return v;
}

__global__ __launch_bounds__(TPB) void chamfer_grid_kernel() {
    extern __shared__ float4 sT[];          // 4096 targets: 64 KB dynamic
    __shared__ float4 sBBxy[NCHK];          // chunk {mnx,mxx,mny,mxy}
    __shared__ float2 sBBz [NCHK];          // chunk {mnz,mxz}
    __shared__ float4 gBBxy[NGRP];          // group boxes
    __shared__ float2 gBBz [NGRP];

    int b    = blockIdx.x >> 3;             // CPB = 8
    int cb   = blockIdx.x & 7;
    int tid  = threadIdx.x;
    int lane = tid & 31;
    int wl   = tid >> 5;                    // 0..15

    const float4* gt = g_tgtS + b * NPTS;
    #pragma unroll
    for (int i = tid; i < NPTS; i += TPB) sT[i] = gt[i];
    __syncthreads();

    // chunk AABBs (tid == chunk id; 512 chunks, TPB = 512)
    {
        float mnx = BIGF, mxx = -BIGF, mny = BIGF, mxy = -BIGF, mnz = BIGF, mxz = -BIGF;
        #pragma unroll
        for (int i = 0; i < CSZ; i++) {
            float4 t = sT[tid * CSZ + i];
            mnx = fminf(mnx, t.x); mxx = fmaxf(mxx, t.x);
            mny = fminf(mny, t.y); mxy = fmaxf(mxy, t.y);
            mnz = fminf(mnz, t.z); mxz = fmaxf(mxz, t.z);
        }
        sBBxy[tid] = make_float4(mnx, mxx, mny, mxy);
        sBBz [tid] = make_float2(mnz, mxz);
    }
    __syncthreads();

    // group AABBs = union of 8 chunk boxes
    if (tid < NGRP) {
        float mnx = BIGF, mxx = -BIGF, mny = BIGF, mxy = -BIGF, mnz = BIGF, mxz = -BIGF;
        #pragma unroll
        for (int c = 0; c < 8; c++) {
            float4 bxy = sBBxy[tid * 8 + c];
            float2 bz  = sBBz [tid * 8 + c];
            mnx = fminf(mnx, bxy.x); mxx = fmaxf(mxx, bxy.y);
            mny = fminf(mny, bxy.z); mxy = fmaxf(mxy, bxy.w);
            mnz = fminf(mnz, bz.x);  mxz = fmaxf(mxz, bz.y);
        }
        gBBxy[tid] = make_float4(mnx, mxx, mny, mxy);
        gBBz [tid] = make_float2(mnz, mxz);
    }
    __syncthreads();

    int wb = wl * CPB + cb;                 // warp block 0..127 (interleaved)
    int ip = wb * 32 + lane;
    float4 p = g_predS[b * NPTS + ip];      // {-x,-y,-z, |p|^2}
    int pidx = g_pidx [b * NPTS + ip];
    float px = -p.x, py = -p.y, pz = -p.z;

    // probe: the 4 rank-matched chunks (32 targets)
    int c0 = 4 * wb;
    float m0 = BIGF, m1 = BIGF;
    eval_chunk8(sT + (c0 + 0) * CSZ, p, m0, m1);
    eval_chunk8(sT + (c0 + 1) * CSZ, p, m0, m1);
    eval_chunk8(sT + (c0 + 2) * CSZ, p, m0, m1);
    eval_chunk8(sT + (c0 + 3) * CSZ, p, m0, m1);
    float d2 = fmaxf(__fmaf_rn(2.0f, fminf(m0, m1), p.w), 0.0f);

    // warp pred box (3D)
    float wmnx = px, wmxx = px, wmny = py, wmxy = py, wmnz = pz, wmxz = pz;
    #pragma unroll
    for (int o = 16; o; o >>= 1) {
        wmnx = fminf(wmnx, __shfl_xor_sync(0xffffffffu, wmnx, o));
        wmxx = fmaxf(wmxx, __shfl_xor_sync(0xffffffffu, wmxx, o));
        wmny = fminf(wmny, __shfl_xor_sync(0xffffffffu, wmny, o));
        wmxy = fmaxf(wmxy, __shfl_xor_sync(0xffffffffu, wmxy, o));
        wmnz = fminf(wmnz, __shfl_xor_sync(0xffffffffu, wmnz, o));
        wmxz = fmaxf(wmxz, __shfl_xor_sync(0xffffffffu, wmxz, o));
    }

    int go = wb >> 1;                       // own group
    unsigned probedBits = 0xFu << ((wb & 1) * 4);   // probed chunks within go

    // --- own group first: remaining L2 chunks, contracting d2 -------------
    {
        float d2m = warp_max(d2);
        int k = go * 8 + (lane & 7);
        float lb = box_lb2(sBBxy[k], sBBz[k], wmnx, wmxx, wmny, wmxy, wmnz, wmxz);
        bool keep = lb <= __fmaf_rn(d2m, 1.0001f, 1e-7f);
        unsigned ms = __ballot_sync(0xffffffffu, keep) & 0xFFu & ~probedBits;
        while (ms) {
            int k2 = go * 8 + (__ffs(ms) - 1);
            ms &= ms - 1;
            float plb = pt_lb2(sBBxy[k2], sBBz[k2], px, py, pz);
            bool need = plb <= __fmaf_rn(d2, 1.0001f, 1e-7f);
            if (__ballot_sync(0xffffffffu, need)) {
                eval_chunk8(sT + k2 * CSZ, p, m0, m1);
                d2 = fmaxf(__fmaf_rn(2.0f, fminf(m0, m1), p.w), 0.0f);
            }
        }
    }

    // --- L1: test all 64 groups (2 ballots) against contracted bound ------
    float d2m = warp_max(d2);
    float thr = __fmaf_rn(d2m, 1.0001f, 1e-7f);
    unsigned gm[2];
    #pragma unroll
    for (int h = 0; h < 2; h++) {
        int g = h * 32 + lane;
        float lb = box_lb2(gBBxy[g], gBBz[g], wmnx, wmxx, wmny, wmxy, wmnz, wmxz);
        gm[h] = __ballot_sync(0xffffffffu, lb <= thr);
    }
    gm[go >> 5] &= ~(1u << (go & 31));

    // --- walk surviving groups; L2 ballot per group, then chunk evals -----
    #pragma unroll 1
    for (int h = 0; h < 2; h++) {
        unsigned gmask = gm[h];
        while (gmask) {
            int g = h * 32 + (__ffs(gmask) - 1);
            gmask &= gmask - 1;
            float d2g = warp_max(d2);
            int k = g * 8 + (lane & 7);
            float lb = box_lb2(sBBxy[k], sBBz[k], wmnx, wmxx, wmny, wmxy, wmnz, wmxz);
            bool keep = lb <= __fmaf_rn(d2g, 1.0001f, 1e-7f);
            unsigned ms = __ballot_sync(0xffffffffu, keep) & 0xFFu;
            while (ms) {
                int k2 = g * 8 + (__ffs(ms) - 1);
                ms &= ms - 1;
                float plb = pt_lb2(sBBxy[k2], sBBz[k2], px, py, pz);
                bool need = plb <= __fmaf_rn(d2, 1.0001f, 1e-7f);
                if (__ballot_sync(0xffffffffu, need)) {
                    eval_chunk8(sT + k2 * CSZ, p, m0, m1);
                    d2 = fmaxf(__fmaf_rn(2.0f, fminf(m0, m1), p.w), 0.0f);
                }
            }
        }
    }

    g_dist[b * NPTS + pidx] = sqrtf(d2);
}

// ---------------------------------------------------------------------------
// Reductions: fixed original-index order -> bitwise deterministic
// ---------------------------------------------------------------------------
__global__ __launch_bounds__(256) void reduce1_kernel() {
    __shared__ float ssum[256];
    int tid = threadIdx.x;
    const int per_block = (BB * NPTS) / NBLK1;   // 1024
    float acc = 0.0f;
    #pragma unroll
    for (int k = 0; k < per_block / 256; k++)
        acc += g_dist[blockIdx.x * per_block + k * 256 + tid];
    ssum[tid] = acc;
    __syncthreads();
    #pragma unroll
    for (int s = 128; s > 0; s >>= 1) {
        if (tid < s) ssum[tid] += ssum[tid + s];
        __syncthreads();
    }
    if (tid == 0) g_bsum[blockIdx.x] = ssum[0];
}

__global__ __launch_bounds__(NBLK1) void reduce2_kernel(float* __restrict__ out) {
    __shared__ float ssum[NBLK1];
    int tid = threadIdx.x;
    ssum[tid] = g_bsum[tid];
    __syncthreads();
    #pragma unroll
    for (int s = NBLK1 / 2; s > 0; s >>= 1) {
        if (tid < s) ssum[tid] += ssum[tid + s];
        __syncthreads();
    }
    if (tid == 0) out[0] = ssum[0] * (1.0f / (float)(BB * NPTS));
}

// ---------------------------------------------------------------------------
extern "C" void kernel_launch(void* const* d_in, const int* in_sizes, int n_in,
                              void* d_out, int out_size) {
    const float* pred   = (const float*)d_in[0];   // [B, N, 3]
    const float* target = (const float*)d_in[1];   // [B, M, 3]
    float* out = (float*)d_out;

    static bool attr_set = false;
    if (!attr_set) {
        cudaFuncSetAttribute(chamfer_grid_kernel,
                             cudaFuncAttributeMaxDynamicSharedMemorySize,
                             NPTS * (int)sizeof(float4));
        attr_set = true;
    }

    bin_kernel<<<BB * 2, 512>>>(pred, target);
    chamfer_grid_kernel<<<BB * CPB, TPB, NPTS * (int)sizeof(float4)>>>();
    reduce1_kernel<<<NBLK1, 256>>>();
    reduce2_kernel<<<1, NBLK1>>>(out);
}

// round 16
// speedup vs baseline: 1.8732x; 1.8732x over previous
#include <cuda_runtime.h>
#include <cstdint>

// Problem constants: B=32, N=M=4096, d=3
#define BB     32
#define NPTS   4096
#define NBINS  256                // 8 x-oct * 8 y-oct * 4 z-quart (equal prob)
#define NCHK   256                // 16-target chunks per batch
#define CSZ    16
#define NGRP   8                  // chunk groups of 32
#define TPB    512
#define CPB    8                  // CTAs per batch  (256 CTAs total)
#define NBLK1  128

#define BIGF 3.4028235e38f

// ---- persistent scratch (no allocations allowed) --------------------------
__device__ float4 g_tgtS [BB * NPTS];   // sorted targets {x, y, z, 0.5|t|^2}
__device__ float4 g_predS[BB * NPTS];   // sorted preds  {-x,-y,-z,  |p|^2}
__device__ int    g_pidx [BB * NPTS];   // original pred index per sorted slot
__device__ float  g_dist [BB * NPTS];   // per-pred nearest distance (orig order)
__device__ float  g_bsum [NBLK1];

// ---------------------------------------------------------------------------
// Equal-probability 3-D key: 8 x-octiles * 8 y-octiles * 4 z-quartiles.
// Exactness never depends on this — all bounds are data-derived AABBs.
// ---------------------------------------------------------------------------
__device__ __forceinline__ int qlvl8(float v) {
    return (v > -1.1503f) + (v > -0.6745f) + (v > -0.3186f) + (v > 0.0f) +
           (v >  0.3186f) + (v >  0.6745f) + (v >  1.1503f);
}
__device__ __forceinline__ int qlvl4(float v) {
    return (v > -0.6745f) + (v > 0.0f) + (v > 0.6745f);
}
__device__ __forceinline__ unsigned sort_key(float x, float y, float z) {
    return (unsigned)((qlvl8(x) * 8 + qlvl8(y)) * 4 + qlvl4(z));
}

// ---------------------------------------------------------------------------
// P1: counting-sort by 3-D cell key. One CTA per (batch, tensor).
// ---------------------------------------------------------------------------
__global__ __launch_bounds__(512) void bin_kernel(const float* __restrict__ pred,
                                                  const float* __restrict__ tgt) {
    __shared__ unsigned hist[NBINS];
    __shared__ unsigned wsum[512];

    int b      = blockIdx.x >> 1;
    int isPred = blockIdx.x & 1;
    const float* src = (isPred ? pred : tgt) + (size_t)b * NPTS * 3;
    int tid = threadIdx.x;

    if (tid < NBINS) hist[tid] = 0u;
    __syncthreads();

    unsigned mybin[8];
    #pragma unroll
    for (int j = 0; j < 8; j++) {
        int i = tid * 8 + j;
        mybin[j] = sort_key(src[3 * i], src[3 * i + 1], src[3 * i + 2]);
        atomicAdd(&hist[mybin[j]], 1u);
    }
    __syncthreads();

    unsigned s = (tid < NBINS) ? hist[tid] : 0u;
    wsum[tid] = s;
    __syncthreads();
    #pragma unroll
    for (int off = 1; off < 512; off <<= 1) {
        unsigned v = wsum[tid];
        unsigned a = (tid >= off) ? wsum[tid - off] : 0u;
        __syncthreads();
        wsum[tid] = v + a;
        __syncthreads();
    }
    if (tid < NBINS) hist[tid] = wsum[tid] - s;   // exclusive base
    __syncthreads();

    float4* dst = (isPred ? g_predS : g_tgtS) + b * NPTS;
    int*    pix = g_pidx + b * NPTS;
    #pragma unroll
    for (int j = 0; j < 8; j++) {
        int i = tid * 8 + j;
        unsigned pos = atomicAdd(&hist[mybin[j]], 1u);
        float x = src[3 * i], y = src[3 * i + 1], z = src[3 * i + 2];
        float n2 = x * x + y * y + z * z;
        if (isPred) {
            dst[pos] = make_float4(-x, -y, -z, n2);
            pix[pos] = i;
        } else {
            dst[pos] = make_float4(x, y, z, 0.5f * n2);
        }
    }
}

// ---------------------------------------------------------------------------
// P2: exact NN, 3-D AABB pruning, contracting near-to-far group walk.
//   r(p,t) = 0.5|t|^2 - p.t  (3 FFMA);  d^2 = |p|^2 + 2 r
// ---------------------------------------------------------------------------
__device__ __forceinline__ void eval_chunk(const float4* __restrict__ ct,
                                           float4 p, float& m0, float& m1) {
    #pragma unroll
    for (int i = 0; i < CSZ; i += 2) {
        float4 ta = ct[i];
        float4 tb = ct[i + 1];
        float ra = __fmaf_rn(p.z, ta.z, ta.w);
        float rb = __fmaf_rn(p.z, tb.z, tb.w);
        ra = __fmaf_rn(p.y, ta.y, ra);
        rb = __fmaf_rn(p.y, tb.y, rb);
        ra = __fmaf_rn(p.x, ta.x, ra);
        rb = __fmaf_rn(p.x, tb.x, rb);
        m0 = fminf(m0, ra);
        m1 = fminf(m1, rb);
    }
}

// 3-D point-to-box squared distance
__device__ __forceinline__ float pt_lb2(float4 bxy, float2 bz,
                                        float px, float py, float pz) {
    float dx = fmaxf(0.0f, fmaxf(bxy.x - px, px - bxy.y));
    float dy = fmaxf(0.0f, fmaxf(bxy.z - py, py - bxy.w));
    float dz = fmaxf(0.0f, fmaxf(bz.x - pz, pz - bz.y));
    return __fmaf_rn(dx, dx, __fmaf_rn(dy, dy, dz * dz));
}

// 3-D box-to-box squared distance (chunk box vs warp box)
__device__ __forceinline__ float box_lb2(float4 bxy, float2 bz,
                                         float wmnx, float wmxx, float wmny,
                                         float wmxy, float wmnz, float wmxz) {
    float dx = fmaxf(0.0f, fmaxf(bxy.x - wmxx, wmnx - bxy.y));
    float dy = fmaxf(0.0f, fmaxf(bxy.z - wmxy, wmny - bxy.w));
    float dz = fmaxf(0.0f, fmaxf(bz.x - wmxz, wmnz - bz.y));
    return __fmaf_rn(dx, dx, __fmaf_rn(dy, dy, dz * dz));
}

__device__ __forceinline__ float warp_max(float v) {
    #pragma unroll
    for (int o = 16; o; o >>= 1)
        v = fmaxf(v, __shfl_xor_sync(0xffffffffu, v, o));
    return v;
}

__global__ __launch_bounds__(TPB) void chamfer_grid_kernel() {
    extern __shared__ float4 sT[];          // 4096 targets: 64 KB dynamic
    __shared__ float4 sBBxy[NCHK];          // chunk {mnx,mxx,mny,mxy}
    __shared__ float2 sBBz [NCHK];          // chunk {mnz,mxz}

    int b    = blockIdx.x >> 3;             // CPB = 8
    int cb   = blockIdx.x & 7;
    int tid  = threadIdx.x;
    int lane = tid & 31;
    int wl   = tid >> 5;                    // 0..15

    const float4* gt = g_tgtS + b * NPTS;
    #pragma unroll
    for (int i = tid; i < NPTS; i += TPB) sT[i] = gt[i];
    __syncthreads();

    if (tid < NCHK) {
        float mnx = BIGF, mxx = -BIGF, mny = BIGF, mxy = -BIGF, mnz = BIGF, mxz = -BIGF;
        #pragma unroll
        for (int i = 0; i < CSZ; i++) {
            float4 t = sT[tid * CSZ + i];
            mnx = fminf(mnx, t.x); mxx = fmaxf(mxx, t.x);
            mny = fminf(mny, t.y); mxy = fmaxf(mxy, t.y);
            mnz = fminf(mnz, t.z); mxz = fmaxf(mxz, t.z);
        }
        sBBxy[tid] = make_float4(mnx, mxx, mny, mxy);
        sBBz [tid] = make_float2(mnz, mxz);
    }
    __syncthreads();

    int wb = wl * CPB + cb;                 // warp block 0..127 (interleaved)
    int ip = wb * 32 + lane;
    float4 p = g_predS[b * NPTS + ip];      // {-x,-y,-z, |p|^2}
    int pidx = g_pidx [b * NPTS + ip];
    float px = -p.x, py = -p.y, pz = -p.z;

    // probe BOTH chunks of the warp's rank range (32 targets)
    int cpair = 2 * wb;
    float m0 = BIGF, m1 = BIGF;
    eval_chunk(sT + cpair * CSZ, p, m0, m1);
    eval_chunk(sT + (cpair + 1) * CSZ, p, m0, m1);
    float d2 = fmaxf(__fmaf_rn(2.0f, fminf(m0, m1), p.w), 0.0f);

    // warp pred box (3-D, fixed)
    float wmnx = px, wmxx = px, wmny = py, wmxy = py, wmnz = pz, wmxz = pz;
    #pragma unroll
    for (int o = 16; o; o >>= 1) {
        wmnx = fminf(wmnx, __shfl_xor_sync(0xffffffffu, wmnx, o));
        wmxx = fmaxf(wmxx, __shfl_xor_sync(0xffffffffu, wmxx, o));
        wmny = fminf(wmny, __shfl_xor_sync(0xffffffffu, wmny, o));
        wmxy = fmaxf(wmxy, __shfl_xor_sync(0xffffffffu, wmxy, o));
        wmnz = fminf(wmnz, __shfl_xor_sync(0xffffffffu, wmnz, o));
        wmxz = fmaxf(wmxz, __shfl_xor_sync(0xffffffffu, wmxz, o));
    }

    // near-to-far group order around the warp's own group
    int go = cpair >> 5;                    // warp-uniform
    int order[NGRP];
    {
        int idx = 0;
        order[idx++] = go;
        for (int d = 1; d < NGRP && idx < NGRP; d++) {
            if (go + d < NGRP) order[idx++] = go + d;
            if (go - d >= 0 && idx < NGRP) order[idx++] = go - d;
        }
    }

    #pragma unroll 1
    for (int oi = 0; oi < NGRP; oi++) {
        int g = order[oi];
        // contracting warp-collective bound
        float d2m = warp_max(d2);
        int k = g * 32 + lane;
        float lbw = box_lb2(sBBxy[k], sBBz[k], wmnx, wmxx, wmny, wmxy, wmnz, wmxz);
        bool keep = lbw <= __fmaf_rn(d2m, 1.0001f, 1e-7f);
        unsigned ms = __ballot_sync(0xffffffffu, keep);
        if (g == go) ms &= ~(3u << (cpair & 31));   // probes already done

        while (ms) {
            int k2 = g * 32 + (__ffs(ms) - 1);
            ms &= ms - 1;
            float lb = pt_lb2(sBBxy[k2], sBBz[k2], px, py, pz);
            bool need = lb <= __fmaf_rn(d2, 1.0001f, 1e-7f);
            if (__ballot_sync(0xffffffffu, need)) {
                eval_chunk(sT + k2 * CSZ, p, m0, m1);
                d2 = fmaxf(__fmaf_rn(2.0f, fminf(m0, m1), p.w), 0.0f);
            }
        }
    }

    g_dist[b * NPTS + pidx] = sqrtf(d2);
}

// ---------------------------------------------------------------------------
// Reductions: fixed original-index order -> bitwise deterministic
// ---------------------------------------------------------------------------
__global__ __launch_bounds__(256) void reduce1_kernel() {
    __shared__ float ssum[256];
    int tid = threadIdx.x;
    const int per_block = (BB * NPTS) / NBLK1;   // 1024
    float acc = 0.0f;
    #pragma unroll
    for (int k = 0; k < per_block / 256; k++)
        acc += g_dist[blockIdx.x * per_block + k * 256 + tid];
    ssum[tid] = acc;
    __syncthreads();
    #pragma unroll
    for (int s = 128; s > 0; s >>= 1) {
        if (tid < s) ssum[tid] += ssum[tid + s];
        __syncthreads();
    }
    if (tid == 0) g_bsum[blockIdx.x] = ssum[0];
}

__global__ __launch_bounds__(NBLK1) void reduce2_kernel(float* __restrict__ out) {
    __shared__ float ssum[NBLK1];
    int tid = threadIdx.x;
    ssum[tid] = g_bsum[tid];
    __syncthreads();
    #pragma unroll
    for (int s = NBLK1 / 2; s > 0; s >>= 1) {
        if (tid < s) ssum[tid] += ssum[tid + s];
        __syncthreads();
    }
    if (tid == 0) out[0] = ssum[0] * (1.0f / (float)(BB * NPTS));
}

// ---------------------------------------------------------------------------
extern "C" void kernel_launch(void* const* d_in, const int* in_sizes, int n_in,
                              void* d_out, int out_size) {
    const float* pred   = (const float*)d_in[0];   // [B, N, 3]
    const float* target = (const float*)d_in[1];   // [B, M, 3]
    float* out = (float*)d_out;

    static bool attr_set = false;
    if (!attr_set) {
        cudaFuncSetAttribute(chamfer_grid_kernel,
                             cudaFuncAttributeMaxDynamicSharedMemorySize,
                             NPTS * (int)sizeof(float4));
        attr_set = true;
    }

    bin_kernel<<<BB * 2, 512>>>(pred, target);
    chamfer_grid_kernel<<<BB * CPB, TPB, NPTS * (int)sizeof(float4)>>>();
    reduce1_kernel<<<NBLK1, 256>>>();
    reduce2_kernel<<<1, NBLK1>>>(out);
}